// round 15
// baseline (speedup 1.0000x reference)
#include <cuda_runtime.h>
#include <cuda_bf16.h>
#include <cstdint>

#define NN 8192

// ---------------- scratch (device globals; no allocations) ------------------
__device__ __align__(128) uint32_t g_adjbits[(size_t)NN * 256];     // 8 MB bitmask
__device__ float g_invdeg[NN];
__device__ unsigned g_colmax[256];                                  // per-feature absmax bits
__device__ __align__(128) signed char g_xTq[(size_t)256 * NN];      // x^T int8
__device__ __align__(128) int g_x1a[(size_t)NN * 256];              // split-K half 0 (s32)
__device__ __align__(128) int g_x1b[(size_t)NN * 256];              // split-K half 1 (s32)
__device__ __align__(128) __nv_bfloat16 g_nx_hi[(size_t)NN * 512];  // [x1|x] hi
__device__ __align__(128) __nv_bfloat16 g_nx_lo[(size_t)NN * 512];  // [x1|x] lo
__device__ __align__(128) __nv_bfloat16 g_Wt_hi[768 * 512];         // W^T hi
__device__ __align__(128) __nv_bfloat16 g_Wt_lo[768 * 512];         // W^T lo

// ---------------- helpers ----------------------------------------------------
__device__ __forceinline__ uint32_t smem_u32(const void* p) {
    uint32_t a;
    asm("{ .reg .u64 t; cvta.to.shared.u64 t, %1; cvt.u32.u64 %0, t; }"
        : "=r"(a) : "l"(p));
    return a;
}
__device__ __forceinline__ void cp16(uint32_t dst, const void* src) {
    asm volatile("cp.async.cg.shared.global [%0], [%1], 16;" :: "r"(dst), "l"(src));
}
__device__ __forceinline__ void cp_commit() {
    asm volatile("cp.async.commit_group;" ::: "memory");
}
template <int N> __device__ __forceinline__ void cp_wait() {
    asm volatile("cp.async.wait_group %0;" :: "n"(N) : "memory");
}
__device__ __forceinline__ void sts16(uint32_t addr, uint32_t v0, uint32_t v1,
                                      uint32_t v2, uint32_t v3) {
    asm volatile("st.shared.v4.u32 [%0], {%1,%2,%3,%4};"
                 :: "r"(addr), "r"(v0), "r"(v1), "r"(v2), "r"(v3) : "memory");
}
__device__ __forceinline__ void ldsm4(uint32_t& r0, uint32_t& r1, uint32_t& r2,
                                      uint32_t& r3, uint32_t addr) {
    asm volatile("ldmatrix.sync.aligned.m8n8.x4.shared.b16 {%0,%1,%2,%3}, [%4];"
                 : "=r"(r0), "=r"(r1), "=r"(r2), "=r"(r3) : "r"(addr));
}
__device__ __forceinline__ void mma16816(float* c, const uint32_t* a,
                                         const uint32_t* b) {
    asm volatile(
        "mma.sync.aligned.m16n8k16.row.col.f32.bf16.bf16.f32 "
        "{%0,%1,%2,%3}, {%4,%5,%6,%7}, {%8,%9}, {%0,%1,%2,%3};"
        : "+f"(c[0]), "+f"(c[1]), "+f"(c[2]), "+f"(c[3])
        : "r"(a[0]), "r"(a[1]), "r"(a[2]), "r"(a[3]), "r"(b[0]), "r"(b[1]));
}
__device__ __forceinline__ void imma16832(int* c, const uint32_t* a,
                                          const uint32_t* b) {
    asm volatile(
        "mma.sync.aligned.m16n8k32.row.col.s32.s8.s8.s32 "
        "{%0,%1,%2,%3}, {%4,%5,%6,%7}, {%8,%9}, {%0,%1,%2,%3};"
        : "+r"(c[0]), "+r"(c[1]), "+r"(c[2]), "+r"(c[3])
        : "r"(a[0]), "r"(a[1]), "r"(a[2]), "r"(a[3]), "r"(b[0]), "r"(b[1]));
}

// warp-tile compute (gemm2): 32(M) x 64(N) x (KK*16)(K), accum c[2][8][4]
template <int KK, int PITCH>
__device__ __forceinline__ void tile_compute(uint32_t aAddr, uint32_t bAddr,
                                             float (&c)[2][8][4]) {
#pragma unroll
    for (int kk = 0; kk < KK; ++kk) {
        uint32_t A[2][4], B[8][2];
        ldsm4(A[0][0], A[0][1], A[0][2], A[0][3], aAddr + kk * 32);
        ldsm4(A[1][0], A[1][1], A[1][2], A[1][3], aAddr + 16 * PITCH + kk * 32);
#pragma unroll
        for (int p = 0; p < 4; ++p) {
            uint32_t r0, r1, r2, r3;
            ldsm4(r0, r1, r2, r3, bAddr + p * 16 * PITCH + kk * 32);
            B[2 * p][0] = r0; B[2 * p][1] = r1;
            B[2 * p + 1][0] = r2; B[2 * p + 1][1] = r3;
        }
#pragma unroll
        for (int mt = 0; mt < 2; ++mt)
#pragma unroll
            for (int nt = 0; nt < 8; ++nt)
                mma16816(c[mt][nt], A[mt], B[nt]);
    }
}

// ---------------- conv: adj int32 -> bitmask + inv degree --------------------
__global__ void __launch_bounds__(256) k_conv(const int* __restrict__ adj) {
    __shared__ int wsum[8];
    const int row = blockIdx.x;
    const int lane = threadIdx.x & 31, w = threadIdx.x >> 5;
    const int* src = adj + (size_t)row * NN + w * 1024 + lane;
    uint32_t* dst = g_adjbits + (size_t)row * 256 + w * 32;
    int cnt = 0;
#pragma unroll 8
    for (int p = 0; p < 32; ++p) {
        int v = src[p * 32];
        uint32_t b = __ballot_sync(0xFFFFFFFFu, v == 1);
        if (lane == 0) { dst[p] = b; cnt += __popc(b); }
    }
    if (lane == 0) wsum[w] = cnt;
    __syncthreads();
    if (threadIdx.x == 0) {
        int t = 0;
#pragma unroll
        for (int i = 0; i < 8; ++i) t += wsum[i];
        g_invdeg[row] = 1.0f / (float)t;
    }
}

// ---------------- scale: per-feature absmax (deterministic atomicMax) -------
__global__ void __launch_bounds__(256) k_scale(const float* __restrict__ x) {
    const int col = threadIdx.x;
    const float* p = x + (size_t)blockIdx.x * 128 * 256 + col;
    float m = 0.0f;
#pragma unroll 4
    for (int r = 0; r < 128; ++r) m = fmaxf(m, fabsf(p[(size_t)r * 256]));
    atomicMax(&g_colmax[col], __float_as_uint(m));
}

// ---------------- prep kernels ----------------------------------------------
__global__ void k_prep_x(const float* __restrict__ x) {
    __shared__ float tile[32][33];
    const int n0 = blockIdx.x * 32, f0 = blockIdx.y * 32;
    const int tx = threadIdx.x, ty = threadIdx.y;
    float v = x[(size_t)(n0 + ty) * 256 + f0 + tx];
    tile[ty][tx] = v;
    __nv_bfloat16 h = __float2bfloat16(v);
    size_t o = (size_t)(n0 + ty) * 512 + 256 + f0 + tx;
    g_nx_hi[o] = h;
    g_nx_lo[o] = __float2bfloat16(v - __bfloat162float(h));
    __syncthreads();
    // transpose + int8 quantize per feature f0+ty
    float vv = tile[tx][ty];
    float mv = __uint_as_float(g_colmax[f0 + ty]);
    int q = 0;
    if (mv > 0.0f) {
        q = __float2int_rn(vv * (127.0f / mv));
        q = max(-127, min(127, q));
    }
    g_xTq[(size_t)(f0 + ty) * NN + n0 + tx] = (signed char)q;
}

__global__ void k_prep_w(const float* __restrict__ w) {
    const int b = blockIdx.x;            // Wt row = k*256 + o
    const int k = b >> 8, o = b & 255;
    const float* src = w + (size_t)k * 512 * 256 + o;
    __nv_bfloat16* dh = g_Wt_hi + (size_t)b * 512;
    __nv_bfloat16* dl = g_Wt_lo + (size_t)b * 512;
    for (int f = threadIdx.x; f < 512; f += 256) {
        float v = src[(size_t)f * 256];
        __nv_bfloat16 h = __float2bfloat16(v);
        dh[f] = h;
        dl[f] = __float2bfloat16(v - __bfloat162float(h));
    }
}

// ---------------- GEMM1: int8 IMMA, split-K x2 -------------------------------
// grid 256 = 64 M-tiles x 2 N-tiles x 2 K-halves. 256 threads, 8 warps (4m x 2n).
// CTA tile 128x128, warp tile 32x64, K-chunk 128 int8 (32 iters per K-half).
// A: bits -> s8 {0,1} smem (double-buffered). B: g_xTq via 4-stage cp.async.
// smem 108 KB -> 2 CTAs/SM. Accumulate exact s32; dequant in k_comb.
#define P1   144u
#define AST  18432u              // A stage: 128 rows * 144
#define AB2  36864u              // 2 A stages; B base
#define BST  18432u              // 4 B stages -> total 110592

__device__ __forceinline__ void g1_cpB(uint32_t sbase, int s, int kc, int n0,
                                       int kz, int tid) {
    const int n = tid >> 1, half = tid & 1;
    const uint32_t dst = sbase + AB2 + s * BST + n * P1 + half * 64;
    const char* src = (const char*)g_xTq + (size_t)(n0 + n) * NN + kz * 4096 +
                      kc * 128 + half * 64;
#pragma unroll
    for (int j = 0; j < 4; ++j) cp16(dst + j * 16, src + j * 16);
}

// expand two 32-bit words -> 64 s8 {0,1} bytes (this thread's half row)
__device__ __forceinline__ void g1_expand(uint32_t sbase, int s, int tid,
                                          uint2 bw2) {
    const uint32_t base = sbase + s * AST + (tid >> 1) * P1 + (tid & 1) * 64;
#pragma unroll
    for (int w = 0; w < 2; ++w) {
        const uint32_t bw = w ? bw2.y : bw2.x;
        uint32_t o[8];
#pragma unroll
        for (int q = 0; q < 8; ++q)
            o[q] = ((bw >> (4 * q)) & 15u) * 0x00204081u & 0x01010101u;
        sts16(base + w * 32 +  0, o[0], o[1], o[2], o[3]);
        sts16(base + w * 32 + 16, o[4], o[5], o[6], o[7]);
    }
}

__global__ void __launch_bounds__(256, 2) k_gemm1() {
    extern __shared__ char smem[];
    const uint32_t sbase = smem_u32(smem);
    const int tid = threadIdx.x, lane = tid & 31, wid = tid >> 5;
    const int wm = wid >> 1, wn = wid & 1;       // 4m x 2n warp grid, 32x64 tiles
    const int bx = blockIdx.x;
    const int m0 = (bx >> 2) * 128, n0 = (bx & 1) * 128, kz = (bx >> 1) & 1;

    // this thread's bit stream: row m0+(tid>>1), uint2 (tid&1) of 4 words/iter
    const uint2* bitp = (const uint2*)(g_adjbits + (size_t)(m0 + (tid >> 1)) * 256 +
                                       kz * 128) + (tid & 1);

    uint2 bits_cur = bitp[0];
    g1_cpB(sbase, 0, 0, n0, kz, tid); cp_commit();
    g1_cpB(sbase, 1, 1, n0, kz, tid); cp_commit();
    g1_cpB(sbase, 2, 2, n0, kz, tid); cp_commit();
    g1_expand(sbase, 0, tid, bits_cur);          // A stage 0 (it=0)
    bits_cur = bitp[2];                          // bits for it=1

    const uint32_t aAddr0 = sbase + (wm * 32 + (lane & 15)) * P1 + (lane >> 4) * 16;
    const uint32_t bAddr0 = sbase + AB2 +
        (wn * 64 + (lane & 15)) * P1 + (lane >> 4) * 16;

    int c[2][8][4] = {};
    for (int it = 0; it < 32; ++it) {
        cp_wait<2>();
        __syncthreads();            // B stage it&3 ready; A stage it&1 written
        if (it + 3 < 32) g1_cpB(sbase, (it + 3) & 3, it + 3, n0, kz, tid);
        cp_commit();
        if (it + 1 < 32) g1_expand(sbase, (it + 1) & 1, tid, bits_cur);
        if (it + 2 < 32) bits_cur = bitp[(it + 2) * 2];

        const uint32_t aA = aAddr0 + (it & 1) * AST;
        const uint32_t bA = bAddr0 + (it & 3) * BST;
#pragma unroll
        for (int kk = 0; kk < 4; ++kk) {       // 4 x k32 = K128
            uint32_t A[2][4], B[8][2];
            ldsm4(A[0][0], A[0][1], A[0][2], A[0][3], aA + kk * 32);
            ldsm4(A[1][0], A[1][1], A[1][2], A[1][3], aA + 16 * P1 + kk * 32);
#pragma unroll
            for (int p = 0; p < 4; ++p) {
                uint32_t r0, r1, r2, r3;
                ldsm4(r0, r1, r2, r3, bA + p * (16 * P1) + kk * 32);
                // tile map: r0 = n rows 0-7/k0-15, r1 = n rows 8-15/k0-15,
                //           r2 = n rows 0-7/k16-31, r3 = n rows 8-15/k16-31.
                // s8 b-frag pairing = same rows, {k0-15, k16-31}:
                B[2 * p][0] = r0; B[2 * p][1] = r2;
                B[2 * p + 1][0] = r1; B[2 * p + 1][1] = r3;
            }
#pragma unroll
            for (int mt = 0; mt < 2; ++mt)
#pragma unroll
                for (int nt = 0; nt < 8; ++nt)
                    imma16832(c[mt][nt], A[mt], B[nt]);
        }
    }

    // epilogue: raw s32 partials to this K-half's buffer
    int* dst = kz ? g_x1b : g_x1a;
    const int r = lane >> 2, q = lane & 3;
#pragma unroll
    for (int mt = 0; mt < 2; ++mt) {
        const int lr = wm * 32 + mt * 16 + r;
        const size_t gm0 = (size_t)(m0 + lr), gm1 = gm0 + 8;
#pragma unroll
        for (int nt = 0; nt < 8; ++nt) {
            const int col = n0 + wn * 64 + nt * 8 + q * 2;
            *(int2*)(dst + gm0 * 256 + col) = make_int2(c[mt][nt][0], c[mt][nt][1]);
            *(int2*)(dst + gm1 * 256 + col) = make_int2(c[mt][nt][2], c[mt][nt][3]);
        }
    }
}

// ---------------- comb: x1 = (a+b)*scale*invdeg -> nx hi/lo ------------------
__global__ void __launch_bounds__(256) k_comb() {
    const int idx = blockIdx.x * 256 + threadIdx.x;      // int4 index
    const int row = idx >> 6;                             // 64 int4 per row
    const int col = (idx & 63) * 4;
    int4 a = ((const int4*)g_x1a)[idx];
    int4 b = ((const int4*)g_x1b)[idx];
    const float inv = g_invdeg[row] * (1.0f / 127.0f);
    float s0 = __uint_as_float(g_colmax[col + 0]) * inv;
    float s1 = __uint_as_float(g_colmax[col + 1]) * inv;
    float s2 = __uint_as_float(g_colmax[col + 2]) * inv;
    float s3 = __uint_as_float(g_colmax[col + 3]) * inv;
    float v0 = (float)(a.x + b.x) * s0, v1 = (float)(a.y + b.y) * s1;
    float v2 = (float)(a.z + b.z) * s2, v3 = (float)(a.w + b.w) * s3;
    __nv_bfloat16 h0 = __float2bfloat16(v0), h1 = __float2bfloat16(v1);
    __nv_bfloat16 h2 = __float2bfloat16(v2), h3 = __float2bfloat16(v3);
    uint2 ph, pl;
    ph.x = ((uint32_t)__bfloat16_as_ushort(h1) << 16) | __bfloat16_as_ushort(h0);
    ph.y = ((uint32_t)__bfloat16_as_ushort(h3) << 16) | __bfloat16_as_ushort(h2);
    __nv_bfloat16 l0 = __float2bfloat16(v0 - __bfloat162float(h0));
    __nv_bfloat16 l1 = __float2bfloat16(v1 - __bfloat162float(h1));
    __nv_bfloat16 l2 = __float2bfloat16(v2 - __bfloat162float(h2));
    __nv_bfloat16 l3 = __float2bfloat16(v3 - __bfloat162float(h3));
    pl.x = ((uint32_t)__bfloat16_as_ushort(l1) << 16) | __bfloat16_as_ushort(l0);
    pl.y = ((uint32_t)__bfloat16_as_ushort(l3) << 16) | __bfloat16_as_ushort(l2);
    *(uint2*)(g_nx_hi + (size_t)row * 512 + col) = ph;
    *(uint2*)(g_nx_lo + (size_t)row * 512 + col) = pl;
}

// ---------------- GEMM2: out[k] = nx @ W[k] + bias (3-term bf16 split) ------
// (unchanged: 66.6us measured)
#define ROWB   80u
#define STG    10240u
#define BOFF   40960u

__device__ __forceinline__ void g2_cp(uint32_t sbase, int s, int it, int m0,
                                      int bn0, int tid) {
    const __nv_bfloat16 *Ap, *Bp;
    int f0;
    if (it < 16)      { Ap = g_nx_hi; Bp = g_Wt_hi; f0 = it * 32; }
    else if (it < 32) { Ap = g_nx_hi; Bp = g_Wt_lo; f0 = (it - 16) * 32; }
    else              { Ap = g_nx_lo; Bp = g_Wt_hi; f0 = 256 + (it - 32) * 32; }
#pragma unroll
    for (int i = 0; i < 2; ++i) {
        int idx = tid + i * 256;
        int rr = idx >> 2, cc = idx & 3;
        cp16(sbase + s * STG + rr * ROWB + cc * 16,
             Ap + (size_t)(m0 + rr) * 512 + f0 + cc * 8);
        cp16(sbase + BOFF + s * STG + rr * ROWB + cc * 16,
             Bp + (size_t)(bn0 + rr) * 512 + f0 + cc * 8);
    }
}

__global__ void __launch_bounds__(256, 2) k_gemm2(const float* __restrict__ bias,
                                                  float* __restrict__ out) {
    extern __shared__ char smem[];
    __shared__ float sbias[128];
    const uint32_t sbase = smem_u32(smem);
    const int tid = threadIdx.x, lane = tid & 31, wid = tid >> 5;
    const int wm = wid >> 1, wn = wid & 1;
    const int bx = blockIdx.x;
    const int m0 = (bx / 6) * 128;
    const int ntile = bx % 6;
    const int kh = ntile >> 1, o0 = (ntile & 1) * 128;
    const int bn0 = kh * 256 + o0;
    if (tid < 128) sbias[tid] = bias[o0 + tid];

    g2_cp(sbase, 0, 0, m0, bn0, tid); cp_commit();
    g2_cp(sbase, 1, 1, m0, bn0, tid); cp_commit();
    g2_cp(sbase, 2, 2, m0, bn0, tid); cp_commit();

    const uint32_t aAddr0 = sbase + (wm * 32 + (lane & 15)) * ROWB + (lane >> 4) * 16;
    const uint32_t bAddr0 = sbase + BOFF +
        (wn * 64 + ((lane >> 4) << 3) + (lane & 7)) * ROWB + ((lane >> 3) & 1) * 16;

    float c[2][8][4] = {};
    for (int it = 0; it < 40; ++it) {
        const int s = it & 3;
        cp_wait<2>();
        __syncthreads();
        if (it + 3 < 40) g2_cp(sbase, (it + 3) & 3, it + 3, m0, bn0, tid);
        cp_commit();
        tile_compute<2, ROWB>(aAddr0 + s * STG, bAddr0 + s * STG, c);
    }

    const int r = lane >> 2, q = lane & 3;
#pragma unroll
    for (int mt = 0; mt < 2; ++mt) {
        const int lr = wm * 32 + mt * 16 + r;
        const size_t gm0 = (size_t)(m0 + lr);
#pragma unroll
        for (int nt = 0; nt < 8; ++nt) {
            const int oc = wn * 64 + nt * 8 + q * 2;
            float2 va = make_float2(c[mt][nt][0] + sbias[oc],
                                    c[mt][nt][1] + sbias[oc + 1]);
            float2 vb = make_float2(c[mt][nt][2] + sbias[oc],
                                    c[mt][nt][3] + sbias[oc + 1]);
            *(float2*)(out + ((size_t)kh * NN + gm0) * 256 + o0 + oc) = va;
            *(float2*)(out + ((size_t)kh * NN + gm0 + 8) * 256 + o0 + oc) = vb;
        }
    }
}

// ---------------- launch -----------------------------------------------------
extern "C" void kernel_launch(void* const* d_in, const int* in_sizes, int n_in,
                              void* d_out, int out_size) {
    const float* x = nullptr;
    const int* adj = nullptr;
    const float* w = nullptr;
    const float* bias = nullptr;
    for (int i = 0; i < n_in; ++i) {
        long sz = in_sizes[i];
        if (sz == (long)NN * 256) x = (const float*)d_in[i];
        else if (sz == (long)NN * NN) adj = (const int*)d_in[i];
        else if (sz == 3L * 512 * 256) w = (const float*)d_in[i];
        else if (sz == 256) bias = (const float*)d_in[i];
    }
    float* out = (float*)d_out;

    cudaFuncSetAttribute(k_gemm1, cudaFuncAttributeMaxDynamicSharedMemorySize, 110592);
    cudaFuncSetAttribute(k_gemm2, cudaFuncAttributeMaxDynamicSharedMemorySize, 81920);

    k_scale<<<64, 256>>>(x);
    k_prep_x<<<dim3(256, 8), dim3(32, 32)>>>(x);
    k_prep_w<<<768, 256>>>(w);
    k_conv<<<NN, 256>>>(adj);
    k_gemm1<<<256, 256, 110592>>>();
    k_comb<<<2048, 256>>>();
    k_gemm2<<<384, 256, 81920>>>(bias, out);
}

// round 16
// speedup vs baseline: 1.8752x; 1.8752x over previous
#include <cuda_runtime.h>
#include <cuda_fp16.h>
#include <cstdint>

#define NN 8192

// ---------------- scratch (device globals; no allocations) ------------------
__device__ __align__(128) uint32_t g_adjbits[(size_t)NN * 256];     // 8 MB bitmask
__device__ float g_invdeg[NN];
__device__ __align__(128) float g_x1a[(size_t)NN * 256];            // split-K half 0
__device__ __align__(128) float g_x1b[(size_t)NN * 256];            // split-K half 1
__device__ __align__(128) __half g_xT[(size_t)256 * NN];            // x^T fp16
__device__ __align__(128) __half g_nx[(size_t)NN * 512];            // [x1|x] fp16
__device__ __align__(128) __half g_Wt[768 * 512];                   // W^T fp16
// ---------------- helpers ----------------------------------------------------
__device__ __forceinline__ uint32_t smem_u32(const void* p) {
    uint32_t a;
    asm("{ .reg .u64 t; cvta.to.shared.u64 t, %1; cvt.u32.u64 %0, t; }"
        : "=r"(a) : "l"(p));
    return a;
}
__device__ __forceinline__ void cp16(uint32_t dst, const void* src) {
    asm volatile("cp.async.cg.shared.global [%0], [%1], 16;" :: "r"(dst), "l"(src));
}
__device__ __forceinline__ void cp_commit() {
    asm volatile("cp.async.commit_group;" ::: "memory");
}
template <int N> __device__ __forceinline__ void cp_wait() {
    asm volatile("cp.async.wait_group %0;" :: "n"(N) : "memory");
}
__device__ __forceinline__ void sts16(uint32_t addr, uint32_t v0, uint32_t v1,
                                      uint32_t v2, uint32_t v3) {
    asm volatile("st.shared.v4.u32 [%0], {%1,%2,%3,%4};"
                 :: "r"(addr), "r"(v0), "r"(v1), "r"(v2), "r"(v3) : "memory");
}
__device__ __forceinline__ void ldsm4(uint32_t& r0, uint32_t& r1, uint32_t& r2,
                                      uint32_t& r3, uint32_t addr) {
    asm volatile("ldmatrix.sync.aligned.m8n8.x4.shared.b16 {%0,%1,%2,%3}, [%4];"
                 : "=r"(r0), "=r"(r1), "=r"(r2), "=r"(r3) : "r"(addr));
}
__device__ __forceinline__ void mma16816(float* c, const uint32_t* a,
                                         const uint32_t* b) {
    asm volatile(
        "mma.sync.aligned.m16n8k16.row.col.f32.f16.f16.f32 "
        "{%0,%1,%2,%3}, {%4,%5,%6,%7}, {%8,%9}, {%0,%1,%2,%3};"
        : "+f"(c[0]), "+f"(c[1]), "+f"(c[2]), "+f"(c[3])
        : "r"(a[0]), "r"(a[1]), "r"(a[2]), "r"(a[3]), "r"(b[0]), "r"(b[1]));
}

// warp-tile compute: 32(M) x 64(N) x (KK*16)(K), accum c[2][8][4]
template <int KK, int PITCH>
__device__ __forceinline__ void tile_compute(uint32_t aAddr, uint32_t bAddr,
                                             float (&c)[2][8][4]) {
#pragma unroll
    for (int kk = 0; kk < KK; ++kk) {
        uint32_t A[2][4], B[8][2];
        ldsm4(A[0][0], A[0][1], A[0][2], A[0][3], aAddr + kk * 32);
        ldsm4(A[1][0], A[1][1], A[1][2], A[1][3], aAddr + 16 * PITCH + kk * 32);
#pragma unroll
        for (int p = 0; p < 4; ++p) {
            uint32_t r0, r1, r2, r3;
            ldsm4(r0, r1, r2, r3, bAddr + p * 16 * PITCH + kk * 32);
            B[2 * p][0] = r0; B[2 * p][1] = r1;
            B[2 * p + 1][0] = r2; B[2 * p + 1][1] = r3;
        }
#pragma unroll
        for (int mt = 0; mt < 2; ++mt)
#pragma unroll
            for (int nt = 0; nt < 8; ++nt)
                mma16816(c[mt][nt], A[mt], B[nt]);
    }
}

// ---------------- conv: adj int32 -> bitmask + inv degree --------------------
__global__ void __launch_bounds__(256) k_conv(const int* __restrict__ adj) {
    __shared__ int wsum[8];
    const int row = blockIdx.x;
    const int lane = threadIdx.x & 31, w = threadIdx.x >> 5;
    const int* src = adj + (size_t)row * NN + w * 1024 + lane;
    uint32_t* dst = g_adjbits + (size_t)row * 256 + w * 32;
    int cnt = 0;
#pragma unroll 8
    for (int p = 0; p < 32; ++p) {
        int v = src[p * 32];
        uint32_t b = __ballot_sync(0xFFFFFFFFu, v == 1);
        if (lane == 0) { dst[p] = b; cnt += __popc(b); }
    }
    if (lane == 0) wsum[w] = cnt;
    __syncthreads();
    if (threadIdx.x == 0) {
        int t = 0;
#pragma unroll
        for (int i = 0; i < 8; ++i) t += wsum[i];
        g_invdeg[row] = 1.0f / (float)t;
    }
}

// ---------------- prep kernels ----------------------------------------------
__global__ void k_prep_x(const float* __restrict__ x) {
    __shared__ float tile[32][33];
    const int n0 = blockIdx.x * 32, f0 = blockIdx.y * 32;
    const int tx = threadIdx.x, ty = threadIdx.y;
    float v = x[(size_t)(n0 + ty) * 256 + f0 + tx];
    tile[ty][tx] = v;
    g_nx[(size_t)(n0 + ty) * 512 + 256 + f0 + tx] = __float2half(v);
    __syncthreads();
    g_xT[(size_t)(f0 + ty) * NN + n0 + tx] = __float2half(tile[tx][ty]);
}

__global__ void k_prep_w(const float* __restrict__ w) {
    const int b = blockIdx.x;            // Wt row = k*256 + o
    const int k = b >> 8, o = b & 255;
    const float* src = w + (size_t)k * 512 * 256 + o;
    __half* dh = g_Wt + (size_t)b * 512;
    for (int f = threadIdx.x; f < 512; f += 256)
        dh[f] = __float2half(src[(size_t)f * 256]);
}

// ---------------- GEMM1: split-K x2, fp16 ------------------------------------
// grid 256 = 64 M-tiles x 2 N-tiles x 2 K-halves. 256 threads, 8 warps (4m x 2n).
// CTA tile 128x128, K-half 4096 in 64 chunks of 64. smem 108 KB -> 2 CTAs/SM.
// A: bits -> smem fp16 {0,1} (double-buffered). B: g_xT via 4-stage cp.async.
#define P1   144u
#define AST  18432u              // A stage: 128 * 144
#define AB2  36864u              // 2 A stages; B base
#define BST  18432u              // 4 B stages -> total 110592

__device__ __forceinline__ void g1_cpB(uint32_t sbase, int s, int kc, int n0,
                                       int kz, int tid) {
    const int row = tid >> 1, half = tid & 1;
    const uint32_t dst = sbase + AB2 + s * BST + row * P1 + half * 64;
    const char* src = (const char*)(g_xT + (size_t)(n0 + row) * NN + kz * 4096 +
                                    kc * 64) + half * 64;
#pragma unroll
    for (int j = 0; j < 4; ++j) cp16(dst + j * 16, src + j * 16);
}

// expand one 32-bit word (32 K-cols of one M-row) into 64B of fp16 smem
__device__ __forceinline__ void g1_expand(uint32_t sbase, int s, int tid,
                                          uint32_t bw) {
    const uint32_t base = sbase + s * AST + (tid >> 1) * P1 + (tid & 1) * 64;
#pragma unroll
    for (int q = 0; q < 4; ++q) {
        uint32_t w0 = ((bw >> (8*q+0)) & 1u) * 0x3C00u | ((bw >> (8*q+1)) & 1u) * 0x3C000000u;
        uint32_t w1 = ((bw >> (8*q+2)) & 1u) * 0x3C00u | ((bw >> (8*q+3)) & 1u) * 0x3C000000u;
        uint32_t w2 = ((bw >> (8*q+4)) & 1u) * 0x3C00u | ((bw >> (8*q+5)) & 1u) * 0x3C000000u;
        uint32_t w3 = ((bw >> (8*q+6)) & 1u) * 0x3C00u | ((bw >> (8*q+7)) & 1u) * 0x3C000000u;
        sts16(base + q * 16, w0, w1, w2, w3);
    }
}

__global__ void __launch_bounds__(256, 2) k_gemm1() {
    extern __shared__ char smem[];
    const uint32_t sbase = smem_u32(smem);
    const int tid = threadIdx.x, lane = tid & 31, wid = tid >> 5;
    const int wm = wid >> 1, wn = wid & 1;       // 4m x 2n warp grid
    const int bx = blockIdx.x;
    const int m0 = (bx >> 2) * 128, n0 = (bx & 1) * 128, kz = (bx >> 1) & 1;

    // this thread's bit stream: row m0+(tid>>1), words kz*128 + it*2 + (tid&1)
    const uint32_t* bitp = g_adjbits + (size_t)(m0 + (tid >> 1)) * 256 +
                           kz * 128 + (tid & 1);

    uint32_t bits_cur = bitp[0];
    g1_cpB(sbase, 0, 0, n0, kz, tid); cp_commit();
    g1_cpB(sbase, 1, 1, n0, kz, tid); cp_commit();
    g1_cpB(sbase, 2, 2, n0, kz, tid); cp_commit();
    g1_expand(sbase, 0, tid, bits_cur);          // A stage 0 (it=0)
    bits_cur = bitp[2];                          // bits for it=1

    const uint32_t aAddr0 = sbase + (wm * 32 + (lane & 15)) * P1 + (lane >> 4) * 16;
    const uint32_t bAddr0 = sbase + AB2 +
        (wn * 64 + ((lane >> 4) << 3) + (lane & 7)) * P1 + ((lane >> 3) & 1) * 16;

    float c[2][8][4] = {};
    for (int it = 0; it < 64; ++it) {
        cp_wait<2>();
        __syncthreads();            // B stage it&3 ready; A stage it&1 written
        if (it + 3 < 64) g1_cpB(sbase, (it + 3) & 3, it + 3, n0, kz, tid);
        cp_commit();
        if (it + 1 < 64) g1_expand(sbase, (it + 1) & 1, tid, bits_cur);
        if (it + 2 < 64) bits_cur = bitp[(it + 2) * 2];

        tile_compute<4, P1>(aAddr0 + (it & 1) * AST,
                            bAddr0 + (it & 3) * BST, c);
    }

    // epilogue: raw fp32 partials to this K-half's buffer
    float* dst = kz ? g_x1b : g_x1a;
    const int r = lane >> 2, q = lane & 3;
#pragma unroll
    for (int mt = 0; mt < 2; ++mt) {
        const int lr = wm * 32 + mt * 16 + r;
        const size_t gm0 = (size_t)(m0 + lr), gm1 = gm0 + 8;
#pragma unroll
        for (int nt = 0; nt < 8; ++nt) {
            const int col = n0 + wn * 64 + nt * 8 + q * 2;
            *(float2*)(dst + gm0 * 256 + col) = make_float2(c[mt][nt][0], c[mt][nt][1]);
            *(float2*)(dst + gm1 * 256 + col) = make_float2(c[mt][nt][2], c[mt][nt][3]);
        }
    }
}

// ---------------- comb: x1 = (a+b)*invdeg -> nx fp16 (cols 0..255) -----------
__global__ void __launch_bounds__(256) k_comb() {
    const int idx = blockIdx.x * 256 + threadIdx.x;      // float4 index
    const int row = idx >> 6;                             // 64 float4 per row
    const int col = (idx & 63) * 4;
    float4 a = ((const float4*)g_x1a)[idx];
    float4 b = ((const float4*)g_x1b)[idx];
    const float inv = g_invdeg[row];
    float v0 = (a.x + b.x) * inv, v1 = (a.y + b.y) * inv;
    float v2 = (a.z + b.z) * inv, v3 = (a.w + b.w) * inv;
    uint2 ph;
    ph.x = ((uint32_t)__half_as_ushort(__float2half(v1)) << 16) |
           __half_as_ushort(__float2half(v0));
    ph.y = ((uint32_t)__half_as_ushort(__float2half(v3)) << 16) |
           __half_as_ushort(__float2half(v2));
    *(uint2*)(g_nx + (size_t)row * 512 + col) = ph;
}

// ---------------- GEMM2: out[k] = nx @ W[k] + bias (single fp16 pass) --------
// 16 K-chunks of 32 (K=512). grid 384 = 64 m x 3 heads x 2 o-tiles.
#define ROWB   80u
#define STG    10240u
#define BOFF   40960u

__device__ __forceinline__ void g2_cp(uint32_t sbase, int s, int it, int m0,
                                      int bn0, int tid) {
    const int f0 = it * 32;
#pragma unroll
    for (int i = 0; i < 2; ++i) {
        int idx = tid + i * 256;
        int rr = idx >> 2, cc = idx & 3;
        cp16(sbase + s * STG + rr * ROWB + cc * 16,
             g_nx + (size_t)(m0 + rr) * 512 + f0 + cc * 8);
        cp16(sbase + BOFF + s * STG + rr * ROWB + cc * 16,
             g_Wt + (size_t)(bn0 + rr) * 512 + f0 + cc * 8);
    }
}

__global__ void __launch_bounds__(256, 2) k_gemm2(const float* __restrict__ bias,
                                                  float* __restrict__ out) {
    extern __shared__ char smem[];
    __shared__ float sbias[128];
    const uint32_t sbase = smem_u32(smem);
    const int tid = threadIdx.x, lane = tid & 31, wid = tid >> 5;
    const int wm = wid >> 1, wn = wid & 1;
    const int bx = blockIdx.x;
    const int m0 = (bx / 6) * 128;
    const int ntile = bx % 6;
    const int kh = ntile >> 1, o0 = (ntile & 1) * 128;
    const int bn0 = kh * 256 + o0;
    if (tid < 128) sbias[tid] = bias[o0 + tid];

    g2_cp(sbase, 0, 0, m0, bn0, tid); cp_commit();
    g2_cp(sbase, 1, 1, m0, bn0, tid); cp_commit();
    g2_cp(sbase, 2, 2, m0, bn0, tid); cp_commit();

    const uint32_t aAddr0 = sbase + (wm * 32 + (lane & 15)) * ROWB + (lane >> 4) * 16;
    const uint32_t bAddr0 = sbase + BOFF +
        (wn * 64 + ((lane >> 4) << 3) + (lane & 7)) * ROWB + ((lane >> 3) & 1) * 16;

    float c[2][8][4] = {};
    for (int it = 0; it < 16; ++it) {
        const int s = it & 3;
        cp_wait<2>();
        __syncthreads();
        if (it + 3 < 16) g2_cp(sbase, (it + 3) & 3, it + 3, m0, bn0, tid);
        cp_commit();
        tile_compute<2, ROWB>(aAddr0 + s * STG, bAddr0 + s * STG, c);
    }

    const int r = lane >> 2, q = lane & 3;
#pragma unroll
    for (int mt = 0; mt < 2; ++mt) {
        const int lr = wm * 32 + mt * 16 + r;
        const size_t gm0 = (size_t)(m0 + lr);
#pragma unroll
        for (int nt = 0; nt < 8; ++nt) {
            const int oc = wn * 64 + nt * 8 + q * 2;
            float2 va = make_float2(c[mt][nt][0] + sbias[oc],
                                    c[mt][nt][1] + sbias[oc + 1]);
            float2 vb = make_float2(c[mt][nt][2] + sbias[oc],
                                    c[mt][nt][3] + sbias[oc + 1]);
            *(float2*)(out + ((size_t)kh * NN + gm0) * 256 + o0 + oc) = va;
            *(float2*)(out + ((size_t)kh * NN + gm0 + 8) * 256 + o0 + oc) = vb;
        }
    }
}

// ---------------- launch -----------------------------------------------------
extern "C" void kernel_launch(void* const* d_in, const int* in_sizes, int n_in,
                              void* d_out, int out_size) {
    const float* x = nullptr;
    const int* adj = nullptr;
    const float* w = nullptr;
    const float* bias = nullptr;
    for (int i = 0; i < n_in; ++i) {
        long sz = in_sizes[i];
        if (sz == (long)NN * 256) x = (const float*)d_in[i];
        else if (sz == (long)NN * NN) adj = (const int*)d_in[i];
        else if (sz == 3L * 512 * 256) w = (const float*)d_in[i];
        else if (sz == 256) bias = (const float*)d_in[i];
    }
    float* out = (float*)d_out;

    cudaFuncSetAttribute(k_gemm1, cudaFuncAttributeMaxDynamicSharedMemorySize, 110592);
    cudaFuncSetAttribute(k_gemm2, cudaFuncAttributeMaxDynamicSharedMemorySize, 81920);

    k_prep_x<<<dim3(256, 8), dim3(32, 32)>>>(x);
    k_prep_w<<<768, 256>>>(w);
    k_conv<<<NN, 256>>>(adj);
    k_gemm1<<<256, 256, 110592>>>();
    k_comb<<<2048, 256>>>();
    k_gemm2<<<384, 256, 81920>>>(bias, out);
}

// round 17
// speedup vs baseline: 1.8775x; 1.0012x over previous
#include <cuda_runtime.h>
#include <cuda_fp16.h>
#include <cstdint>

#define NN 8192

// ---------------- scratch (device globals; no allocations) ------------------
__device__ __align__(128) uint32_t g_adjbits[(size_t)NN * 256];     // 8 MB bitmask
__device__ float g_invdeg[NN];
__device__ __align__(128) float g_x1a[(size_t)NN * 256];            // split-K half 0
__device__ __align__(128) float g_x1b[(size_t)NN * 256];            // split-K half 1
__device__ __align__(128) __half g_xT[(size_t)256 * NN];            // x^T fp16
__device__ __align__(128) __half g_nx[(size_t)NN * 512];            // [x1|x] fp16
__device__ __align__(128) __half g_Wt[768 * 512];                   // W^T fp16
// ---------------- helpers ----------------------------------------------------
__device__ __forceinline__ uint32_t smem_u32(const void* p) {
    uint32_t a;
    asm("{ .reg .u64 t; cvta.to.shared.u64 t, %1; cvt.u32.u64 %0, t; }"
        : "=r"(a) : "l"(p));
    return a;
}
__device__ __forceinline__ void cp16(uint32_t dst, const void* src) {
    asm volatile("cp.async.cg.shared.global [%0], [%1], 16;" :: "r"(dst), "l"(src));
}
__device__ __forceinline__ void cp_commit() {
    asm volatile("cp.async.commit_group;" ::: "memory");
}
template <int N> __device__ __forceinline__ void cp_wait() {
    asm volatile("cp.async.wait_group %0;" :: "n"(N) : "memory");
}
__device__ __forceinline__ void sts16(uint32_t addr, uint32_t v0, uint32_t v1,
                                      uint32_t v2, uint32_t v3) {
    asm volatile("st.shared.v4.u32 [%0], {%1,%2,%3,%4};"
                 :: "r"(addr), "r"(v0), "r"(v1), "r"(v2), "r"(v3) : "memory");
}
__device__ __forceinline__ void ldsm4(uint32_t& r0, uint32_t& r1, uint32_t& r2,
                                      uint32_t& r3, uint32_t addr) {
    asm volatile("ldmatrix.sync.aligned.m8n8.x4.shared.b16 {%0,%1,%2,%3}, [%4];"
                 : "=r"(r0), "=r"(r1), "=r"(r2), "=r"(r3) : "r"(addr));
}
__device__ __forceinline__ void mma16816(float* c, const uint32_t* a,
                                         const uint32_t* b) {
    asm volatile(
        "mma.sync.aligned.m16n8k16.row.col.f32.f16.f16.f32 "
        "{%0,%1,%2,%3}, {%4,%5,%6,%7}, {%8,%9}, {%0,%1,%2,%3};"
        : "+f"(c[0]), "+f"(c[1]), "+f"(c[2]), "+f"(c[3])
        : "r"(a[0]), "r"(a[1]), "r"(a[2]), "r"(a[3]), "r"(b[0]), "r"(b[1]));
}
// fp16-accumulator variant (full-rate HMMA candidate)
__device__ __forceinline__ void mma16816h(uint32_t* c, const uint32_t* a,
                                          const uint32_t* b) {
    asm volatile(
        "mma.sync.aligned.m16n8k16.row.col.f16.f16.f16.f16 "
        "{%0,%1}, {%2,%3,%4,%5}, {%6,%7}, {%0,%1};"
        : "+r"(c[0]), "+r"(c[1])
        : "r"(a[0]), "r"(a[1]), "r"(a[2]), "r"(a[3]), "r"(b[0]), "r"(b[1]));
}

// warp-tile compute (gemm2): 32(M) x 64(N) x (KK*16)(K), accum c[2][8][4]
template <int KK, int PITCH>
__device__ __forceinline__ void tile_compute(uint32_t aAddr, uint32_t bAddr,
                                             float (&c)[2][8][4]) {
#pragma unroll
    for (int kk = 0; kk < KK; ++kk) {
        uint32_t A[2][4], B[8][2];
        ldsm4(A[0][0], A[0][1], A[0][2], A[0][3], aAddr + kk * 32);
        ldsm4(A[1][0], A[1][1], A[1][2], A[1][3], aAddr + 16 * PITCH + kk * 32);
#pragma unroll
        for (int p = 0; p < 4; ++p) {
            uint32_t r0, r1, r2, r3;
            ldsm4(r0, r1, r2, r3, bAddr + p * 16 * PITCH + kk * 32);
            B[2 * p][0] = r0; B[2 * p][1] = r1;
            B[2 * p + 1][0] = r2; B[2 * p + 1][1] = r3;
        }
#pragma unroll
        for (int mt = 0; mt < 2; ++mt)
#pragma unroll
            for (int nt = 0; nt < 8; ++nt)
                mma16816(c[mt][nt], A[mt], B[nt]);
    }
}

// ---------------- conv: adj int32 -> bitmask + inv degree --------------------
__global__ void __launch_bounds__(256) k_conv(const int* __restrict__ adj) {
    __shared__ int wsum[8];
    const int row = blockIdx.x;
    const int lane = threadIdx.x & 31, w = threadIdx.x >> 5;
    const int* src = adj + (size_t)row * NN + w * 1024 + lane;
    uint32_t* dst = g_adjbits + (size_t)row * 256 + w * 32;
    int cnt = 0;
#pragma unroll 8
    for (int p = 0; p < 32; ++p) {
        int v = src[p * 32];
        uint32_t b = __ballot_sync(0xFFFFFFFFu, v == 1);
        if (lane == 0) { dst[p] = b; cnt += __popc(b); }
    }
    if (lane == 0) wsum[w] = cnt;
    __syncthreads();
    if (threadIdx.x == 0) {
        int t = 0;
#pragma unroll
        for (int i = 0; i < 8; ++i) t += wsum[i];
        g_invdeg[row] = 1.0f / (float)t;
    }
}

// ---------------- prep kernels ----------------------------------------------
__global__ void k_prep_x(const float* __restrict__ x) {
    __shared__ float tile[32][33];
    const int n0 = blockIdx.x * 32, f0 = blockIdx.y * 32;
    const int tx = threadIdx.x, ty = threadIdx.y;
    float v = x[(size_t)(n0 + ty) * 256 + f0 + tx];
    tile[ty][tx] = v;
    g_nx[(size_t)(n0 + ty) * 512 + 256 + f0 + tx] = __float2half(v);
    __syncthreads();
    g_xT[(size_t)(f0 + ty) * NN + n0 + tx] = __float2half(tile[tx][ty]);
}

__global__ void k_prep_w(const float* __restrict__ w) {
    const int b = blockIdx.x;            // Wt row = k*256 + o
    const int k = b >> 8, o = b & 255;
    const float* src = w + (size_t)k * 512 * 256 + o;
    __half* dh = g_Wt + (size_t)b * 512;
    for (int f = threadIdx.x; f < 512; f += 256)
        dh[f] = __float2half(src[(size_t)f * 256]);
}

// ---------------- GEMM1: split-K x2, fp16 MMA + fp16 accumulators ------------
// grid 256 = 64 M-tiles x 2 N-tiles x 2 K-halves. 256 threads, 8 warps (4m x 2n).
// CTA tile 128x128, K-half 4096 in 64 chunks of 64. smem 108 KB -> 2 CTAs/SM.
// A: bits -> smem fp16 {0,1} (double-buffered). B: g_xT via 4-stage cp.async.
#define P1   144u
#define AST  18432u              // A stage: 128 * 144
#define AB2  36864u              // 2 A stages; B base
#define BST  18432u              // 4 B stages -> total 110592

__device__ __forceinline__ void g1_cpB(uint32_t sbase, int s, int kc, int n0,
                                       int kz, int tid) {
    const int row = tid >> 1, half = tid & 1;
    const uint32_t dst = sbase + AB2 + s * BST + row * P1 + half * 64;
    const char* src = (const char*)(g_xT + (size_t)(n0 + row) * NN + kz * 4096 +
                                    kc * 64) + half * 64;
#pragma unroll
    for (int j = 0; j < 4; ++j) cp16(dst + j * 16, src + j * 16);
}

// expand one 32-bit word (32 K-cols of one M-row) into 64B of fp16 smem
__device__ __forceinline__ void g1_expand(uint32_t sbase, int s, int tid,
                                          uint32_t bw) {
    const uint32_t base = sbase + s * AST + (tid >> 1) * P1 + (tid & 1) * 64;
#pragma unroll
    for (int q = 0; q < 4; ++q) {
        uint32_t w0 = ((bw >> (8*q+0)) & 1u) * 0x3C00u | ((bw >> (8*q+1)) & 1u) * 0x3C000000u;
        uint32_t w1 = ((bw >> (8*q+2)) & 1u) * 0x3C00u | ((bw >> (8*q+3)) & 1u) * 0x3C000000u;
        uint32_t w2 = ((bw >> (8*q+4)) & 1u) * 0x3C00u | ((bw >> (8*q+5)) & 1u) * 0x3C000000u;
        uint32_t w3 = ((bw >> (8*q+6)) & 1u) * 0x3C00u | ((bw >> (8*q+7)) & 1u) * 0x3C000000u;
        sts16(base + q * 16, w0, w1, w2, w3);
    }
}

__global__ void __launch_bounds__(256, 2) k_gemm1() {
    extern __shared__ char smem[];
    const uint32_t sbase = smem_u32(smem);
    const int tid = threadIdx.x, lane = tid & 31, wid = tid >> 5;
    const int wm = wid >> 1, wn = wid & 1;       // 4m x 2n warp grid
    const int bx = blockIdx.x;
    const int m0 = (bx >> 2) * 128, n0 = (bx & 1) * 128, kz = (bx >> 1) & 1;

    // this thread's bit stream: row m0+(tid>>1), words kz*128 + it*2 + (tid&1)
    const uint32_t* bitp = g_adjbits + (size_t)(m0 + (tid >> 1)) * 256 +
                           kz * 128 + (tid & 1);

    uint32_t bits_cur = bitp[0];
    g1_cpB(sbase, 0, 0, n0, kz, tid); cp_commit();
    g1_cpB(sbase, 1, 1, n0, kz, tid); cp_commit();
    g1_cpB(sbase, 2, 2, n0, kz, tid); cp_commit();
    g1_expand(sbase, 0, tid, bits_cur);          // A stage 0 (it=0)
    bits_cur = bitp[2];                          // bits for it=1

    const uint32_t aAddr0 = sbase + (wm * 32 + (lane & 15)) * P1 + (lane >> 4) * 16;
    const uint32_t bAddr0 = sbase + AB2 +
        (wn * 64 + ((lane >> 4) << 3) + (lane & 7)) * P1 + ((lane >> 3) & 1) * 16;

    uint32_t c[2][8][2] = {};                     // fp16x2 accumulators
    for (int it = 0; it < 64; ++it) {
        cp_wait<2>();
        __syncthreads();            // B stage it&3 ready; A stage it&1 written
        if (it + 3 < 64) g1_cpB(sbase, (it + 3) & 3, it + 3, n0, kz, tid);
        cp_commit();
        if (it + 1 < 64) g1_expand(sbase, (it + 1) & 1, tid, bits_cur);
        if (it + 2 < 64) bits_cur = bitp[(it + 2) * 2];

        const uint32_t aA = aAddr0 + (it & 1) * AST;
        const uint32_t bA = bAddr0 + (it & 3) * BST;
#pragma unroll
        for (int kk = 0; kk < 4; ++kk) {
            uint32_t A[2][4], B[8][2];
            ldsm4(A[0][0], A[0][1], A[0][2], A[0][3], aA + kk * 32);
            ldsm4(A[1][0], A[1][1], A[1][2], A[1][3], aA + 16 * P1 + kk * 32);
#pragma unroll
            for (int p = 0; p < 4; ++p) {
                uint32_t r0, r1, r2, r3;
                ldsm4(r0, r1, r2, r3, bA + p * (16 * P1) + kk * 32);
                B[2 * p][0] = r0; B[2 * p][1] = r1;
                B[2 * p + 1][0] = r2; B[2 * p + 1][1] = r3;
            }
#pragma unroll
            for (int mt = 0; mt < 2; ++mt)
#pragma unroll
                for (int nt = 0; nt < 8; ++nt)
                    mma16816h(c[mt][nt], A[mt], B[nt]);
        }
    }

    // epilogue: unpack half2 -> fp32 partials to this K-half's buffer
    float* dst = kz ? g_x1b : g_x1a;
    const int r = lane >> 2, q = lane & 3;
#pragma unroll
    for (int mt = 0; mt < 2; ++mt) {
        const int lr = wm * 32 + mt * 16 + r;
        const size_t gm0 = (size_t)(m0 + lr), gm1 = gm0 + 8;
#pragma unroll
        for (int nt = 0; nt < 8; ++nt) {
            const int col = n0 + wn * 64 + nt * 8 + q * 2;
            __half2 h0 = *(__half2*)&c[mt][nt][0];   // rows r,  cols 2q,2q+1
            __half2 h1 = *(__half2*)&c[mt][nt][1];   // rows r+8
            *(float2*)(dst + gm0 * 256 + col) =
                make_float2(__half2float(h0.x), __half2float(h0.y));
            *(float2*)(dst + gm1 * 256 + col) =
                make_float2(__half2float(h1.x), __half2float(h1.y));
        }
    }
}

// ---------------- comb: x1 = (a+b)*invdeg -> nx fp16 (cols 0..255) -----------
__global__ void __launch_bounds__(256) k_comb() {
    const int idx = blockIdx.x * 256 + threadIdx.x;      // float4 index
    const int row = idx >> 6;                             // 64 float4 per row
    const int col = (idx & 63) * 4;
    float4 a = ((const float4*)g_x1a)[idx];
    float4 b = ((const float4*)g_x1b)[idx];
    const float inv = g_invdeg[row];
    float v0 = (a.x + b.x) * inv, v1 = (a.y + b.y) * inv;
    float v2 = (a.z + b.z) * inv, v3 = (a.w + b.w) * inv;
    uint2 ph;
    ph.x = ((uint32_t)__half_as_ushort(__float2half(v1)) << 16) |
           __half_as_ushort(__float2half(v0));
    ph.y = ((uint32_t)__half_as_ushort(__float2half(v3)) << 16) |
           __half_as_ushort(__float2half(v2));
    *(uint2*)(g_nx + (size_t)row * 512 + col) = ph;
}

// ---------------- GEMM2: out[k] = nx @ W[k] + bias (single fp16 pass) --------
// 16 K-chunks of 32 (K=512). grid 384 = 64 m x 3 heads x 2 o-tiles.
#define ROWB   80u
#define STG    10240u
#define BOFF   40960u

__device__ __forceinline__ void g2_cp(uint32_t sbase, int s, int it, int m0,
                                      int bn0, int tid) {
    const int f0 = it * 32;
#pragma unroll
    for (int i = 0; i < 2; ++i) {
        int idx = tid + i * 256;
        int rr = idx >> 2, cc = idx & 3;
        cp16(sbase + s * STG + rr * ROWB + cc * 16,
             g_nx + (size_t)(m0 + rr) * 512 + f0 + cc * 8);
        cp16(sbase + BOFF + s * STG + rr * ROWB + cc * 16,
             g_Wt + (size_t)(bn0 + rr) * 512 + f0 + cc * 8);
    }
}

__global__ void __launch_bounds__(256, 2) k_gemm2(const float* __restrict__ bias,
                                                  float* __restrict__ out) {
    extern __shared__ char smem[];
    __shared__ float sbias[128];
    const uint32_t sbase = smem_u32(smem);
    const int tid = threadIdx.x, lane = tid & 31, wid = tid >> 5;
    const int wm = wid >> 1, wn = wid & 1;
    const int bx = blockIdx.x;
    const int m0 = (bx / 6) * 128;
    const int ntile = bx % 6;
    const int kh = ntile >> 1, o0 = (ntile & 1) * 128;
    const int bn0 = kh * 256 + o0;
    if (tid < 128) sbias[tid] = bias[o0 + tid];

    g2_cp(sbase, 0, 0, m0, bn0, tid); cp_commit();
    g2_cp(sbase, 1, 1, m0, bn0, tid); cp_commit();
    g2_cp(sbase, 2, 2, m0, bn0, tid); cp_commit();

    const uint32_t aAddr0 = sbase + (wm * 32 + (lane & 15)) * ROWB + (lane >> 4) * 16;
    const uint32_t bAddr0 = sbase + BOFF +
        (wn * 64 + ((lane >> 4) << 3) + (lane & 7)) * ROWB + ((lane >> 3) & 1) * 16;

    float c[2][8][4] = {};
    for (int it = 0; it < 16; ++it) {
        const int s = it & 3;
        cp_wait<2>();
        __syncthreads();
        if (it + 3 < 16) g2_cp(sbase, (it + 3) & 3, it + 3, m0, bn0, tid);
        cp_commit();
        tile_compute<2, ROWB>(aAddr0 + s * STG, bAddr0 + s * STG, c);
    }

    const int r = lane >> 2, q = lane & 3;
#pragma unroll
    for (int mt = 0; mt < 2; ++mt) {
        const int lr = wm * 32 + mt * 16 + r;
        const size_t gm0 = (size_t)(m0 + lr);
#pragma unroll
        for (int nt = 0; nt < 8; ++nt) {
            const int oc = wn * 64 + nt * 8 + q * 2;
            float2 va = make_float2(c[mt][nt][0] + sbias[oc],
                                    c[mt][nt][1] + sbias[oc + 1]);
            float2 vb = make_float2(c[mt][nt][2] + sbias[oc],
                                    c[mt][nt][3] + sbias[oc + 1]);
            *(float2*)(out + ((size_t)kh * NN + gm0) * 256 + o0 + oc) = va;
            *(float2*)(out + ((size_t)kh * NN + gm0 + 8) * 256 + o0 + oc) = vb;
        }
    }
}

// ---------------- launch -----------------------------------------------------
extern "C" void kernel_launch(void* const* d_in, const int* in_sizes, int n_in,
                              void* d_out, int out_size) {
    const float* x = nullptr;
    const int* adj = nullptr;
    const float* w = nullptr;
    const float* bias = nullptr;
    for (int i = 0; i < n_in; ++i) {
        long sz = in_sizes[i];
        if (sz == (long)NN * 256) x = (const float*)d_in[i];
        else if (sz == (long)NN * NN) adj = (const int*)d_in[i];
        else if (sz == 3L * 512 * 256) w = (const float*)d_in[i];
        else if (sz == 256) bias = (const float*)d_in[i];
    }
    float* out = (float*)d_out;

    cudaFuncSetAttribute(k_gemm1, cudaFuncAttributeMaxDynamicSharedMemorySize, 110592);
    cudaFuncSetAttribute(k_gemm2, cudaFuncAttributeMaxDynamicSharedMemorySize, 81920);

    k_prep_x<<<dim3(256, 8), dim3(32, 32)>>>(x);
    k_prep_w<<<768, 256>>>(w);
    k_conv<<<NN, 256>>>(adj);
    k_gemm1<<<256, 256, 110592>>>();
    k_comb<<<2048, 256>>>();
    k_gemm2<<<384, 256, 81920>>>(bias, out);
}